// round 10
// baseline (speedup 1.0000x reference)
#include <cuda_runtime.h>
#include <cstdint>

#define COLS    24576
#define TPB     512
#define NWARP   (TPB / 32)          // 16
#define VPT     (COLS / (TPB * 4))  // 12 float4 per thread
#define CANDCAP 1024

__device__ __forceinline__ unsigned sortable_u(unsigned b) {
    return b ^ ((unsigned)((int)b >> 31) | 0x80000000u);
}

__global__ __launch_bounds__(TPB) void topk_mask_kernel(
    const float* __restrict__ x, const int* __restrict__ kptr, float* __restrict__ out)
{
    __shared__ unsigned long long candKey[CANDCAP];
    __shared__ int   sh_nc;
    __shared__ int   red[NWARP];
    __shared__ int   sh_tot;
    __shared__ unsigned sh_ucut;
    __shared__ int   sh_icut;

    const int tid  = threadIdx.x;
    const int lane = tid & 31;
    const int warp = tid >> 5;
    const unsigned lmlt = (1u << lane) - 1u;     // lanemask_lt
    const size_t rbase = (size_t)blockIdx.x * COLS;
    const float4* rx = reinterpret_cast<const float4*>(x + rbase);
    float4*       ro = reinterpret_cast<float4*>(out + rbase);

    int k = kptr ? kptr[0] : 64;
    k = max(1, min(k, COLS));

    if (tid == 0) sh_nc = 0;
    __syncthreads();                             // sh_nc=0 visible to all atomics

    // ------- Single read pass: branchless ballot collect, warp-agg append ----
    const float THR = 2.25f;   // E[#candidates] ~ 300/row for N(0,1)
    #pragma unroll
    for (int i = 0; i < VPT; i++) {
        const int v4 = tid + i * TPB;
        const float4 f = __ldcs(rx + v4);
        const int base = v4 * 4;
        const float vals[4] = {f.x, f.y, f.z, f.w};
        #pragma unroll
        for (int j = 0; j < 4; j++) {
            const bool m = vals[j] >= THR;
            const unsigned bal = __ballot_sync(0xffffffffu, m);
            if (bal) {                            // warp-uniform branch
                const int leader = __ffs(bal) - 1;
                int wbase = 0;
                if (lane == leader)
                    wbase = atomicAdd(&sh_nc, __popc(bal));
                wbase = __shfl_sync(0xffffffffu, wbase, leader);
                if (m) {
                    const int pos = wbase + __popc(bal & lmlt);
                    if (pos < CANDCAP) {
                        const unsigned u = __float_as_uint(vals[j]) | 0x80000000u; // >0
                        // value-descending, index-ascending (stable top_k order)
                        candKey[pos] = ((unsigned long long)u << 15)
                                       | (unsigned)(0x7FFF - (base + j));
                    }
                }
            }
        }
    }

    // ------- Zero-fill output row (independent; drains during ranking) -------
    const float4 z4 = make_float4(0.f, 0.f, 0.f, 0.f);
    #pragma unroll
    for (int i = 0; i < VPT; i++)
        __stcs(ro + tid + i * TPB, z4);

    __syncthreads();   // candKey complete; zero stores ordered before scatter

    const int  m    = min(sh_nc, CANDCAP);
    const bool fail = (sh_nc > CANDCAP) || (m < k);

    if (!fail) {
        // -------- rank-by-count; winners (rank < k) scatter directly ---------
        for (int j = tid; j < m; j += TPB) {
            const unsigned long long kj = candKey[j];
            int r = 0;
            for (int i = 0; i < m; i++) r += (candKey[i] > kj) ? 1 : 0;
            if (r < k) {
                const int idx = 0x7FFF - (int)(kj & 0x7FFFull);
                out[rbase + idx] =
                    __uint_as_float((unsigned)(kj >> 15) & 0x7FFFFFFFu);
            }
        }
        return;
    }

    // ---------------- exact fallback (any data): bisection + scatter ---------
    {
        auto blockSum = [&](int c) -> int {
            #pragma unroll
            for (int d = 16; d; d >>= 1) c += __shfl_down_sync(0xffffffffu, c, d);
            __syncthreads();
            if (lane == 0) red[warp] = c;
            __syncthreads();
            if (tid == 0) {
                int t = 0;
                for (int w = 0; w < NWARP; w++) t += red[w];
                sh_tot = t;
            }
            __syncthreads();
            return sh_tot;
        };
        auto countGE = [&](unsigned v) -> int {
            int c = 0;
            for (int i = 0; i < VPT; i++) {
                const float4 f = rx[tid + i * TPB];
                c += (sortable_u(__float_as_uint(f.x)) >= v);
                c += (sortable_u(__float_as_uint(f.y)) >= v);
                c += (sortable_u(__float_as_uint(f.z)) >= v);
                c += (sortable_u(__float_as_uint(f.w)) >= v);
            }
            return blockSum(c);
        };
        auto countEQLE = [&](unsigned v, int idxle) -> int {
            int c = 0;
            for (int i = 0; i < VPT; i++) {
                const int v4 = tid + i * TPB;
                const float4 f = rx[v4];
                const int base = v4 * 4;
                c += (sortable_u(__float_as_uint(f.x)) == v && base + 0 <= idxle);
                c += (sortable_u(__float_as_uint(f.y)) == v && base + 1 <= idxle);
                c += (sortable_u(__float_as_uint(f.z)) == v && base + 2 <= idxle);
                c += (sortable_u(__float_as_uint(f.w)) == v && base + 3 <= idxle);
            }
            return blockSum(c);
        };

        unsigned lo = 0u, hi = 0xFFFFFFFFu;      // max v with countGE(v) >= k
        while (lo < hi) {
            const unsigned mid = lo + ((hi - lo) >> 1) + 1u;
            if (countGE(mid) >= k) lo = mid; else hi = mid - 1u;
        }
        const unsigned ucut = lo;
        const int cgt  = (ucut == 0xFFFFFFFFu) ? 0 : countGE(ucut + 1u);
        const int need = k - cgt;
        int l2 = 0, h2 = COLS - 1;               // smallest idx with countEQLE >= need
        while (l2 < h2) {
            const int mid = (l2 + h2) >> 1;
            if (countEQLE(ucut, mid) >= need) h2 = mid; else l2 = mid + 1;
        }
        if (tid == 0) { sh_ucut = ucut; sh_icut = l2; }
        __syncthreads();

        const unsigned ucut2 = sh_ucut;
        const int      icut2 = sh_icut;
        // scatter winners over the zero-filled row (reads hit L2)
        for (int i = 0; i < VPT; i++) {
            const int v4 = tid + i * TPB;
            const float4 f = __ldcs(rx + v4);
            const int base = v4 * 4;
            const float vals[4] = {f.x, f.y, f.z, f.w};
            #pragma unroll
            for (int j = 0; j < 4; j++) {
                const unsigned u = sortable_u(__float_as_uint(vals[j]));
                if (u > ucut2 || (u == ucut2 && base + j <= icut2))
                    out[rbase + base + j] = vals[j];
            }
        }
    }
}

extern "C" void kernel_launch(void* const* d_in, const int* in_sizes, int n_in,
                              void* d_out, int out_size)
{
    const float* x  = (const float*)d_in[0];
    const int*   kp = (n_in >= 2) ? (const int*)d_in[1] : nullptr;
    const int rows = in_sizes[0] / COLS;
    if (rows <= 0) return;
    topk_mask_kernel<<<rows, TPB>>>(x, kp, (float*)d_out);
}

// round 11
// speedup vs baseline: 1.1481x; 1.1481x over previous
#include <cuda_runtime.h>
#include <cstdint>

#define COLS    24576
#define TPB     512
#define NWARP   (TPB / 32)          // 16
#define VPT     (COLS / (TPB * 4))  // 12 float4 per thread
#define SEGCAP  64
#define CANDCAP (NWARP * SEGCAP)    // 1024

__device__ __forceinline__ unsigned sortable_u(unsigned b) {
    return b ^ ((unsigned)((int)b >> 31) | 0x80000000u);
}

__global__ __launch_bounds__(TPB) void topk_mask_kernel(
    const float* __restrict__ x, const int* __restrict__ kptr, float* __restrict__ out)
{
    __shared__ unsigned long long segKey[CANDCAP];
    __shared__ unsigned long long candKey[CANDCAP];
    __shared__ int segCnt[NWARP];
    __shared__ int segOff[NWARP];
    __shared__ int red[NWARP];
    __shared__ int sh_m;
    __shared__ int sh_fail;
    __shared__ int sh_tot;
    __shared__ unsigned sh_ucut;
    __shared__ int sh_icut;

    const int tid  = threadIdx.x;
    const int lane = tid & 31;
    const int warp = tid >> 5;
    const size_t rbase = (size_t)blockIdx.x * COLS;
    const float4* rx = reinterpret_cast<const float4*>(x + rbase);
    float4*       ro = reinterpret_cast<float4*>(out + rbase);

    int k = kptr ? kptr[0] : 64;
    k = max(1, min(k, COLS));

    if (tid == 0) sh_fail = 0;
    __syncthreads();

    // ---- Pass 1 (R5-style): stream row, segment-collect candidates >= THR ---
    // No atomics, no shfl in the loop: ballot + popc keeps a warp-uniform
    // running count; each hit lane computes its slot from the ballot prefix.
    const float THR = 2.5f;   // E[#candidates] ~ 153/row; P(row < 64 cands) ~ 3e-13
    int cnt = 0;
    #pragma unroll
    for (int i = 0; i < VPT; i++) {
        const int v4 = tid + i * TPB;
        const float4 f = rx[v4];
        const int base = v4 * 4;
        const float vals[4] = {f.x, f.y, f.z, f.w};
        #pragma unroll
        for (int j = 0; j < 4; j++) {
            const bool m = vals[j] >= THR;
            const unsigned bal = __ballot_sync(0xffffffffu, m);
            if (m) {
                const int pos = cnt + __popc(bal & ((1u << lane) - 1u));
                if (pos < SEGCAP) {
                    const unsigned u = __float_as_uint(vals[j]) | 0x80000000u; // >0
                    // value-descending, index-ascending (stable top_k order)
                    segKey[warp * SEGCAP + pos] =
                        ((unsigned long long)u << 15) | (unsigned)(0x7FFF - (base + j));
                }
            }
            cnt += __popc(bal);
        }
    }

    // ---- Zero-fill output row (independent stores; drain during ranking) ----
    const float4 z4 = make_float4(0.f, 0.f, 0.f, 0.f);
    #pragma unroll
    for (int i = 0; i < VPT; i++)
        __stcs(ro + tid + i * TPB, z4);

    if (lane == 0) {
        segCnt[warp] = min(cnt, SEGCAP);
        if (cnt > SEGCAP) sh_fail = 1;
    }
    __syncthreads();

    // prefix-sum of per-warp counts (warp 0)
    if (warp == 0) {
        int c = (lane < NWARP) ? segCnt[lane] : 0;
        int s = c;
        #pragma unroll
        for (int d = 1; d < 32; d <<= 1) {
            int t = __shfl_up_sync(0xffffffffu, s, d);
            if (lane >= d) s += t;
        }
        if (lane < NWARP) segOff[lane] = s - c;
        if (lane == NWARP - 1) sh_m = s;
    }
    __syncthreads();

    const int m = sh_m;
    const bool fail = (sh_fail != 0) || (m < k);   // block-uniform

    if (!fail) {
        // compact segments into contiguous candKey
        {
            const int c = segCnt[warp], off = segOff[warp];
            for (int j = lane; j < c; j += 32)
                candKey[off + j] = segKey[warp * SEGCAP + j];
        }
        __syncthreads();
        // rank-by-count over ~153 unique keys; winners scatter directly
        for (int j = tid; j < m; j += TPB) {
            const unsigned long long kj = candKey[j];
            int r = 0;
            for (int i = 0; i < m; i++) r += (candKey[i] > kj) ? 1 : 0;
            if (r < k) {
                const int idx = 0x7FFF - (int)(kj & 0x7FFFull);
                out[rbase + idx] =
                    __uint_as_float((unsigned)(kj >> 15) & 0x7FFFFFFFu);
            }
        }
        return;
    }

    // ---------------- exact fallback (any data): bisection + scatter ---------
    {
        auto blockSum = [&](int c) -> int {
            #pragma unroll
            for (int d = 16; d; d >>= 1) c += __shfl_down_sync(0xffffffffu, c, d);
            __syncthreads();
            if (lane == 0) red[warp] = c;
            __syncthreads();
            if (tid == 0) {
                int t = 0;
                for (int w = 0; w < NWARP; w++) t += red[w];
                sh_tot = t;
            }
            __syncthreads();
            return sh_tot;
        };
        auto countGE = [&](unsigned v) -> int {
            int c = 0;
            for (int i = 0; i < VPT; i++) {
                const float4 f = rx[tid + i * TPB];
                c += (sortable_u(__float_as_uint(f.x)) >= v);
                c += (sortable_u(__float_as_uint(f.y)) >= v);
                c += (sortable_u(__float_as_uint(f.z)) >= v);
                c += (sortable_u(__float_as_uint(f.w)) >= v);
            }
            return blockSum(c);
        };
        auto countEQLE = [&](unsigned v, int idxle) -> int {
            int c = 0;
            for (int i = 0; i < VPT; i++) {
                const int v4 = tid + i * TPB;
                const float4 f = rx[v4];
                const int base = v4 * 4;
                c += (sortable_u(__float_as_uint(f.x)) == v && base + 0 <= idxle);
                c += (sortable_u(__float_as_uint(f.y)) == v && base + 1 <= idxle);
                c += (sortable_u(__float_as_uint(f.z)) == v && base + 2 <= idxle);
                c += (sortable_u(__float_as_uint(f.w)) == v && base + 3 <= idxle);
            }
            return blockSum(c);
        };

        unsigned lo = 0u, hi = 0xFFFFFFFFu;      // max v with countGE(v) >= k
        while (lo < hi) {
            const unsigned mid = lo + ((hi - lo) >> 1) + 1u;
            if (countGE(mid) >= k) lo = mid; else hi = mid - 1u;
        }
        const unsigned ucut = lo;
        const int cgt  = (ucut == 0xFFFFFFFFu) ? 0 : countGE(ucut + 1u);
        const int need = k - cgt;
        int l2 = 0, h2 = COLS - 1;               // smallest idx with countEQLE >= need
        while (l2 < h2) {
            const int mid = (l2 + h2) >> 1;
            if (countEQLE(ucut, mid) >= need) h2 = mid; else l2 = mid + 1;
        }
        if (tid == 0) { sh_ucut = ucut; sh_icut = l2; }
        __syncthreads();

        const unsigned ucut2 = sh_ucut;
        const int      icut2 = sh_icut;
        // scatter winners over the zero-filled row (reads hit L2)
        for (int i = 0; i < VPT; i++) {
            const int v4 = tid + i * TPB;
            const float4 f = __ldcs(rx + v4);
            const int base = v4 * 4;
            const float vals[4] = {f.x, f.y, f.z, f.w};
            #pragma unroll
            for (int j = 0; j < 4; j++) {
                const unsigned u = sortable_u(__float_as_uint(vals[j]));
                if (u > ucut2 || (u == ucut2 && base + j <= icut2))
                    out[rbase + base + j] = vals[j];
            }
        }
    }
}

extern "C" void kernel_launch(void* const* d_in, const int* in_sizes, int n_in,
                              void* d_out, int out_size)
{
    const float* x  = (const float*)d_in[0];
    const int*   kp = (n_in >= 2) ? (const int*)d_in[1] : nullptr;
    const int rows = in_sizes[0] / COLS;
    if (rows <= 0) return;
    topk_mask_kernel<<<rows, TPB>>>(x, kp, (float*)d_out);
}

// round 12
// speedup vs baseline: 1.5136x; 1.3184x over previous
#include <cuda_runtime.h>
#include <cstdint>

#define COLS    24576
#define TPB     512
#define NWARP   (TPB / 32)          // 16
#define VPT     (COLS / (TPB * 4))  // 12 float4 per thread
#define SEGCAP  64
#define CANDCAP (NWARP * SEGCAP)    // 1024

__device__ __forceinline__ unsigned sortable_u(unsigned b) {
    return b ^ ((unsigned)((int)b >> 31) | 0x80000000u);
}

__global__ __launch_bounds__(TPB, 2) void topk_mask_kernel(
    const float* __restrict__ x, const int* __restrict__ kptr, float* __restrict__ out)
{
    __shared__ unsigned long long segKey[CANDCAP];
    __shared__ unsigned long long candKey[CANDCAP];
    __shared__ int segCnt[NWARP];
    __shared__ int segOff[NWARP];
    __shared__ int red[NWARP];
    __shared__ int sh_m;
    __shared__ int sh_fail;
    __shared__ int sh_tot;
    __shared__ unsigned sh_ucut;
    __shared__ int sh_icut;

    const int tid  = threadIdx.x;
    const int lane = tid & 31;
    const int warp = tid >> 5;
    const size_t rbase = (size_t)blockIdx.x * COLS;
    const float4* rx = reinterpret_cast<const float4*>(x + rbase);
    float4*       ro = reinterpret_cast<float4*>(out + rbase);

    int k = kptr ? kptr[0] : 64;
    k = max(1, min(k, COLS));

    if (tid == 0) sh_fail = 0;
    __syncthreads();

    // ---- Pass 1: stream row, segment-collect candidates >= THR --------------
    // No atomics, no shfl in the loop: ballot + popc keeps a warp-uniform
    // running count; each hit lane computes its slot from the ballot prefix.
    const float THR = 2.5f;   // E[#candidates] ~ 153/row; P(row < 64 cands) ~ 3e-13
    int cnt = 0;
    #pragma unroll
    for (int i = 0; i < VPT; i++) {
        const int v4 = tid + i * TPB;
        const float4 f = rx[v4];
        const int base = v4 * 4;
        const float vals[4] = {f.x, f.y, f.z, f.w};
        #pragma unroll
        for (int j = 0; j < 4; j++) {
            const bool m = vals[j] >= THR;
            const unsigned bal = __ballot_sync(0xffffffffu, m);
            if (m) {
                const int pos = cnt + __popc(bal & ((1u << lane) - 1u));
                if (pos < SEGCAP) {
                    const unsigned u = __float_as_uint(vals[j]) | 0x80000000u; // >0
                    // value-descending, index-ascending (stable top_k order)
                    segKey[warp * SEGCAP + pos] =
                        ((unsigned long long)u << 15) | (unsigned)(0x7FFF - (base + j));
                }
            }
            cnt += __popc(bal);
        }
    }

    // ---- Zero-fill output row (independent stores; drain during ranking) ----
    const float4 z4 = make_float4(0.f, 0.f, 0.f, 0.f);
    #pragma unroll
    for (int i = 0; i < VPT; i++)
        __stcs(ro + tid + i * TPB, z4);

    if (lane == 0) {
        segCnt[warp] = min(cnt, SEGCAP);
        if (cnt > SEGCAP) sh_fail = 1;
    }
    __syncthreads();

    // prefix-sum of per-warp counts (warp 0)
    if (warp == 0) {
        int c = (lane < NWARP) ? segCnt[lane] : 0;
        int s = c;
        #pragma unroll
        for (int d = 1; d < 32; d <<= 1) {
            int t = __shfl_up_sync(0xffffffffu, s, d);
            if (lane >= d) s += t;
        }
        if (lane < NWARP) segOff[lane] = s - c;
        if (lane == NWARP - 1) sh_m = s;
    }
    __syncthreads();

    const int m = sh_m;
    const bool fail = (sh_fail != 0) || (m < k);   // block-uniform

    if (!fail) {
        // compact segments into contiguous candKey
        {
            const int c = segCnt[warp], off = segOff[warp];
            for (int j = lane; j < c; j += 32)
                candKey[off + j] = segKey[warp * SEGCAP + j];
        }
        __syncthreads();
        // rank-by-count over ~153 unique keys; winners scatter directly
        for (int j = tid; j < m; j += TPB) {
            const unsigned long long kj = candKey[j];
            int r = 0;
            for (int i = 0; i < m; i++) r += (candKey[i] > kj) ? 1 : 0;
            if (r < k) {
                const int idx = 0x7FFF - (int)(kj & 0x7FFFull);
                out[rbase + idx] =
                    __uint_as_float((unsigned)(kj >> 15) & 0x7FFFFFFFu);
            }
        }
        return;
    }

    // ---------------- exact fallback (any data): bisection + scatter ---------
    {
        auto blockSum = [&](int c) -> int {
            #pragma unroll
            for (int d = 16; d; d >>= 1) c += __shfl_down_sync(0xffffffffu, c, d);
            __syncthreads();
            if (lane == 0) red[warp] = c;
            __syncthreads();
            if (tid == 0) {
                int t = 0;
                for (int w = 0; w < NWARP; w++) t += red[w];
                sh_tot = t;
            }
            __syncthreads();
            return sh_tot;
        };
        auto countGE = [&](unsigned v) -> int {
            int c = 0;
            for (int i = 0; i < VPT; i++) {
                const float4 f = rx[tid + i * TPB];
                c += (sortable_u(__float_as_uint(f.x)) >= v);
                c += (sortable_u(__float_as_uint(f.y)) >= v);
                c += (sortable_u(__float_as_uint(f.z)) >= v);
                c += (sortable_u(__float_as_uint(f.w)) >= v);
            }
            return blockSum(c);
        };
        auto countEQLE = [&](unsigned v, int idxle) -> int {
            int c = 0;
            for (int i = 0; i < VPT; i++) {
                const int v4 = tid + i * TPB;
                const float4 f = rx[v4];
                const int base = v4 * 4;
                c += (sortable_u(__float_as_uint(f.x)) == v && base + 0 <= idxle);
                c += (sortable_u(__float_as_uint(f.y)) == v && base + 1 <= idxle);
                c += (sortable_u(__float_as_uint(f.z)) == v && base + 2 <= idxle);
                c += (sortable_u(__float_as_uint(f.w)) == v && base + 3 <= idxle);
            }
            return blockSum(c);
        };

        unsigned lo = 0u, hi = 0xFFFFFFFFu;      // max v with countGE(v) >= k
        while (lo < hi) {
            const unsigned mid = lo + ((hi - lo) >> 1) + 1u;
            if (countGE(mid) >= k) lo = mid; else hi = mid - 1u;
        }
        const unsigned ucut = lo;
        const int cgt  = (ucut == 0xFFFFFFFFu) ? 0 : countGE(ucut + 1u);
        const int need = k - cgt;
        int l2 = 0, h2 = COLS - 1;               // smallest idx with countEQLE >= need
        while (l2 < h2) {
            const int mid = (l2 + h2) >> 1;
            if (countEQLE(ucut, mid) >= need) h2 = mid; else l2 = mid + 1;
        }
        if (tid == 0) { sh_ucut = ucut; sh_icut = l2; }
        __syncthreads();

        const unsigned ucut2 = sh_ucut;
        const int      icut2 = sh_icut;
        // scatter winners over the zero-filled row (reads hit L2)
        for (int i = 0; i < VPT; i++) {
            const int v4 = tid + i * TPB;
            const float4 f = __ldcs(rx + v4);
            const int base = v4 * 4;
            const float vals[4] = {f.x, f.y, f.z, f.w};
            #pragma unroll
            for (int j = 0; j < 4; j++) {
                const unsigned u = sortable_u(__float_as_uint(vals[j]));
                if (u > ucut2 || (u == ucut2 && base + j <= icut2))
                    out[rbase + base + j] = vals[j];
            }
        }
    }
}

extern "C" void kernel_launch(void* const* d_in, const int* in_sizes, int n_in,
                              void* d_out, int out_size)
{
    const float* x  = (const float*)d_in[0];
    const int*   kp = (n_in >= 2) ? (const int*)d_in[1] : nullptr;
    const int rows = in_sizes[0] / COLS;
    if (rows <= 0) return;
    topk_mask_kernel<<<rows, TPB>>>(x, kp, (float*)d_out);
}